// round 14
// baseline (speedup 1.0000x reference)
#include <cuda_runtime.h>

#define BB 8
#define CC 19
#define HH 384
#define WW 384
#define HW (HH*WW)
#define NPIX (BB*HW)
#define NBLK 1152           /* x 256 thr x 4 px = NPIX exactly; <=8/SM co-resident */
#define NTHR 256
#define DBOUND 777          /* B+C+H+W, the reference's init */

__device__ unsigned char g_pred[NPIX];
__device__ unsigned char g_tb[NPIX];
__device__ int g_list[NPIX];          /* pixels with tb==0 (only ones with dist>0) */
__device__ float g_cep[NBLK];
__device__ unsigned int g_nlist = 0u;
__device__ unsigned int g_bar = 0u;
__device__ unsigned long long g_packed = 0ull;  /* [63:16]=border sum, [15:0]=count */

__device__ __forceinline__ void bar_arrive_release() {
    unsigned dummy;
    asm volatile("atom.add.release.gpu.global.u32 %0, [%1], 1;"
                 : "=r"(dummy) : "l"(&g_bar) : "memory");
}
__device__ __forceinline__ unsigned bar_poll_acquire() {
    unsigned v;
    asm volatile("ld.acquire.gpu.global.u32 %0, [%1];"
                 : "=r"(v) : "l"(&g_bar) : "memory");
    return v;
}

// vertical 1D border distance (L2-direct), early exit, capped at `cap` (exact)
__device__ __forceinline__ int vdist(const unsigned char* __restrict__ tbb,
                                     int y, int xx, int cap) {
    for (int k = 0; k < cap; k++) {
        int yu = y - k, yd = y + k;
        bool inb = false;
        if (yu >= 0)           { inb = true; if (__ldcg(tbb + yu * WW + xx)) return k; }
        if (yd < HH && k != 0) { inb = true; if (__ldcg(tbb + yd * WW + xx)) return k; }
        if (!inb) break;
    }
    return cap;
}

// ---------------------------------------------------------------------------
// ONE persistent kernel, 1152 co-resident blocks (<=32 regs via bounds(256,8)).
// Phase 1: 4 px/thread float4 channel streaming (4KB contiguous DRAM burst per
//   block per channel -> row-buffer locality). Lean accumulators: s[4] + mantissa-
//   embedded argmax me[4] (<4e-6 perturbation); v[tgt] re-fetched post-loop
//   (L1/L2 hit). Pixels with tb==0 (~0.6%) pushed to a candidate list.
// Fence-free device barrier (release/acquire -- no CCTL.IVALL L1 flush).
// Phase 2: only list entries (~7k px): pred-border check + exact separable
//   Chebyshev DT with early exit. Packed {sum,count} atomic fuses the final.
// ---------------------------------------------------------------------------
__global__ __launch_bounds__(NTHR, 8) void k_fused(const float* __restrict__ x,
                                                   const int* __restrict__ t,
                                                   float* __restrict__ out) {
    const int tid = threadIdx.x;
    const int p = (blockIdx.x * NTHR + tid) * 4;
    const int b = p / HW, hw = p - b * HW;
    const int y = hw / WW, xx = hw - y * WW;   // xx multiple of 4

    // ---------------- Phase 1: CE + pred + tb + candidate list ----------------
    int4 ti4 = *(const int4*)(t + p);
    int ti[4] = { ti4.x, ti4.y, ti4.z, ti4.w };
    const float* xp = x + (size_t)b * (CC * HW) + hw;

    float s[4], me[4];
    {
        float4 v = __ldg((const float4*)xp);
        float vv[4] = { v.x, v.y, v.z, v.w };
#pragma unroll
        for (int i = 0; i < 4; i++) {
            me[i] = __uint_as_float(__float_as_uint(vv[i]) & 0xFFFFFFE0u);
            s[i] = __expf(me[i]);
        }
    }
#pragma unroll
    for (int c = 1; c < CC; c++) {
        float4 v = __ldg((const float4*)(xp + (size_t)c * HW));
        float vv[4] = { v.x, v.y, v.z, v.w };
#pragma unroll
        for (int i = 0; i < 4; i++) {
            float f = __uint_as_float((__float_as_uint(vv[i]) & 0xFFFFFFE0u)
                                      | (unsigned)c);
            me[i] = fmaxf(me[i], f);
            s[i] += __expf(f);
        }
    }

    float nll = 0.f;
    unsigned char prb[4];
#pragma unroll
    for (int i = 0; i < 4; i++) {
        prb[i] = (unsigned char)(__float_as_uint(me[i]) & 31u);
        int tg = ti[i];
        if (tg != 255) {
            float vt = __ldg(xp + (size_t)tg * HW + i);  // cache hit (line loaded)
            nll += __logf(s[i]) - vt;
        }
    }
    *(uchar4*)(g_pred + p) = make_uchar4(prb[0], prb[1], prb[2], prb[3]);

    // target border map + candidate list (tb==0 <=> dist>0 possible)
    bool hasdown = (y < HH - 1);
    int td[4] = { 0, 0, 0, 0 };
    if (hasdown) {
        int4 td4 = *(const int4*)(t + p + WW);
        td[0] = td4.x; td[1] = td4.y; td[2] = td4.z; td[3] = td4.w;
    }
    bool hasR4 = (xx + 4 < WW);
    int tR = hasR4 ? t[p + 4] : 0;
    unsigned char tbb4[4];
#pragma unroll
    for (int i = 0; i < 4; i++) {
        int d = 0;
        if (hasdown) d += td[i] - ti[i];
        if (i < 3) d += ti[i + 1] - ti[i];
        else if (hasR4) d += tR - ti[3];
        tbb4[i] = (unsigned char)(d != 0);
        if (d == 0) {
            unsigned idx = atomicAdd(&g_nlist, 1u);
            g_list[idx] = p + i;
        }
    }
    *(uchar4*)(g_tb + p) = make_uchar4(tbb4[0], tbb4[1], tbb4[2], tbb4[3]);

    // block-reduce CE partial
    {
        float r = nll;
#pragma unroll
        for (int o = 16; o; o >>= 1) r += __shfl_down_sync(0xffffffffu, r, o);
        __shared__ float ws[8];
        if ((tid & 31) == 0) ws[tid >> 5] = r;
        __syncthreads();
        if (tid == 0) {
            float s2 = 0.f;
#pragma unroll
            for (int i = 0; i < 8; i++) s2 += ws[i];
            g_cep[blockIdx.x] = s2;
        }
    }

    // ---------------- device-wide barrier (fence-free) ----------------
    __syncthreads();
    if (tid == 0) {
        bar_arrive_release();
        while (bar_poll_acquire() < NBLK) __nanosleep(64);
    }
    __syncthreads();

    // ---------------- Phase 2: border loss over candidate list ----------------
    unsigned n = __ldcg(&g_nlist);
    int sum = 0;
    for (unsigned i = blockIdx.x * NTHR + tid; i < n; i += NBLK * NTHR) {
        int q = __ldcg(&g_list[i]);
        int qb = q / HW, qhw = q - qb * HW;
        int qy = qhw / WW, qx = qhw - qy * WW;
        int pr = __ldcg(g_pred + q);
        int d = 0;
        if (qy < HH - 1) d += (int)__ldcg(g_pred + q + WW) - pr;
        if (qx < WW - 1) d += (int)__ldcg(g_pred + q + 1)  - pr;
        if (d != 0) {
            const unsigned char* tbb = g_tb + qb * HW;
            int best = vdist(tbb, qy, qx, DBOUND);
            for (int k = 1; k < best; k++) {
                int xl = qx - k, xr = qx + k;
                bool inb = false;
                if (xl >= 0) {
                    inb = true;
                    int c = vdist(tbb, qy, xl, best);
                    c = c > k ? c : k;
                    if (c < best) best = c;
                }
                if (xr < WW) {
                    inb = true;
                    int c = vdist(tbb, qy, xr, best);
                    c = c > k ? c : k;
                    if (c < best) best = c;
                }
                if (!inb) break;
            }
            sum += best;
        }
    }

    int r = sum;
#pragma unroll
    for (int o = 16; o; o >>= 1) r += __shfl_down_sync(0xffffffffu, r, o);
    __shared__ int wsum[8];
    if ((tid & 31) == 0) wsum[tid >> 5] = r;
    __syncthreads();

    __shared__ bool amLast;
    __shared__ long long totBd;
    if (tid == 0) {
        int s2 = 0;
#pragma unroll
        for (int i = 0; i < 8; i++) s2 += wsum[i];
        unsigned long long pkt = ((unsigned long long)(unsigned int)s2 << 16) | 1ull;
        unsigned long long old = atomicAdd(&g_packed, pkt);
        amLast = ((old & 0xFFFFull) == (unsigned long long)(NBLK - 1));
        totBd = (long long)((old >> 16) + (unsigned long long)(unsigned int)s2);
    }
    __syncthreads();

    if (amLast) {
        double ce = 0.0;
        for (int i = tid; i < NBLK; i += NTHR) ce += (double)__ldcg(g_cep + i);
#pragma unroll
        for (int o = 16; o; o >>= 1) ce += __shfl_down_sync(0xffffffffu, ce, o);
        __shared__ double cs[8];
        if ((tid & 31) == 0) cs[tid >> 5] = ce;
        __syncthreads();
        if (tid == 0) {
            double c2 = 0.0;
#pragma unroll
            for (int i = 0; i < 8; i++) c2 += cs[i];
            out[0] = (float)(c2 + 0.2 * (double)totBd);
            g_bar = 0u;                       // reset for next graph replay
            g_nlist = 0u;
            atomicExch(&g_packed, 0ull);
        }
    }
}

extern "C" void kernel_launch(void* const* d_in, const int* in_sizes, int n_in,
                              void* d_out, int out_size) {
    const float* slices = (const float*)d_in[0];
    const int* targets = (const int*)d_in[1];
    float* out = (float*)d_out;
    k_fused<<<NBLK, NTHR>>>(slices, targets, out);
}